// round 7
// baseline (speedup 1.0000x reference)
#include <cuda_runtime.h>
#include <cstdint>
#include <cstddef>

// ============================================================================
// Problem constants
// ============================================================================
static constexpr int BB  = 16;
static constexpr int SQ  = 2048;
static constexpr int DD  = 128;
static constexpr float QK_SCALE = 0.08838834764831845f;  // 1/sqrt(128)

// SMEM layout (bytes), per CTA (2 CTAs/SM):
// Q: 64x128 tf32 words, pair-permuted+swizzled (32 KB)
// K,V: double-buffered 32x128 word tiles (16 KB each buffer)
// M: double-buffered mask tiles, 64 rows x 32 byte-cols, 40B pitch
static constexpr int OFF_Q  = 0;
static constexpr int OFF_K  = 32768;     // + p*16384
static constexpr int OFF_V  = 65536;     // + p*16384
static constexpr int OFF_M  = 98304;     // + p*2560
static constexpr int M_PITCH = 40;
static constexpr int SMEM_TOTAL = OFF_M + 2 * 2560;   // 103424 B

// ============================================================================
// Device globals: pre-converted tf32 K/V in tile-ready layout (no cudaMalloc)
// ============================================================================
__device__ uint32_t g_K[(size_t)BB * SQ * DD];   // pair-permuted + swizzled
__device__ uint32_t g_V[(size_t)BB * SQ * DD];   // swizzled

// ============================================================================
// Helpers
// ============================================================================
__device__ __forceinline__ uint32_t smem_u32(const void* p) {
    uint32_t a;
    asm("{ .reg .u64 t; cvta.to.shared.u64 t, %1; cvt.u32.u64 %0, t; }"
        : "=r"(a) : "l"(p));
    return a;
}

__device__ __forceinline__ uint32_t f2tf32(float f) {
    uint32_t r;
    asm("cvt.rna.tf32.f32 %0, %1;" : "=r"(r) : "f"(f));
    return r;
}

__device__ __forceinline__ void cp16(uint32_t dst, const void* src) {
    asm volatile("cp.async.cg.shared.global [%0], [%1], 16;"
                 :: "r"(dst), "l"(src) : "memory");
}
#define CP_COMMIT() asm volatile("cp.async.commit_group;" ::: "memory")
#define CP_WAIT0()  asm volatile("cp.async.wait_group 0;" ::: "memory")

__device__ __forceinline__ void mma_tf32(float& c0, float& c1, float& c2, float& c3,
                                         uint32_t a0, uint32_t a1, uint32_t a2, uint32_t a3,
                                         uint32_t b0, uint32_t b1) {
    asm volatile(
        "mma.sync.aligned.m16n8k8.row.col.f32.tf32.tf32.f32 "
        "{%0,%1,%2,%3}, {%4,%5,%6,%7}, {%8,%9}, {%0,%1,%2,%3};"
        : "+f"(c0), "+f"(c1), "+f"(c2), "+f"(c3)
        : "r"(a0), "r"(a1), "r"(a2), "r"(a3), "r"(b0), "r"(b1));
}

// ============================================================================
// Kernel 0: K/V fp32 -> tf32 pre-conversion into scratch, tile-ready layout.
// V: word idx = row*128 + (c ^ ((row&3)<<3))          [row = kpos mod 32]
// K: word idx = row*128 + ((pp(c)) ^ ((row&3)<<3)), pp = per-8-group perm
//    (0,4,1,5,2,6,3,7) making (t, t+4) fragment pairs adjacent for LDS.64.
// grid (1048576/256, 2): y=0 -> V (linear read, swizzled write),
//                        y=1 -> K (gathered read, linear write).
// ============================================================================
__global__ void __launch_bounds__(256)
cvt_kernel(const float* __restrict__ Kg, const float* __restrict__ Vg) {
    const uint32_t n = blockIdx.x * 256 + threadIdx.x;
    const uint32_t w = n * 4;
    const uint32_t r = (w >> 7) & 31;
    if (blockIdx.y == 0) {
        float4 v = *(const float4*)(Vg + w);
        uint4 o;
        o.x = f2tf32(v.x); o.y = f2tf32(v.y); o.z = f2tf32(v.z); o.w = f2tf32(v.w);
        uint32_t c = w & 127;
        *(uint4*)(g_V + (w & ~127u) + (c ^ ((r & 3) << 3))) = o;
    } else {
        uint32_t dcol = w & 127;
        uint32_t gL = (((dcol >> 3) ^ (r & 3)) << 3);    // logical 8-col group base
        uint32_t rowbase = w & ~127u;
        const float* src = Kg + rowbase + gL;
        uint4 o;
        if (((dcol >> 2) & 1) == 0) {
            o.x = f2tf32(src[0]); o.y = f2tf32(src[4]);
            o.z = f2tf32(src[1]); o.w = f2tf32(src[5]);
        } else {
            o.x = f2tf32(src[2]); o.y = f2tf32(src[6]);
            o.z = f2tf32(src[3]); o.w = f2tf32(src[7]);
        }
        *(uint4*)(g_K + w) = o;
    }
}

// ============================================================================
// Kernel A: flash attention. grid = (SQ/64, BB), 128 threads (4 warps),
// 2 CTAs/SM. Warp owns 16 q-rows; 64 k-tiles of 32 kpos, cp.async
// double-buffered from pre-converted scratch. Fuses attn normalization.
// ============================================================================
__global__ void __launch_bounds__(128, 2)
attn_kernel(const float* __restrict__ Qg, const void* __restrict__ maskg,
            float* __restrict__ outg, float* __restrict__ attng, int has_attn) {
    extern __shared__ char smem[];
    const uint32_t sb = smem_u32(smem);
    uint32_t* const Qs = (uint32_t*)(smem + OFF_Q);

    const int tid = threadIdx.x, wid = tid >> 5, lane = tid & 31;
    const int g = lane >> 2, t = lane & 3;          // mma groupID / threadID
    const int qt = blockIdx.x, b = blockIdx.y;

    // ---- inline mask dtype detection (bool/uint8 vs int32) ----
    int bad = 0;
    { uint32_t w = ((const uint32_t*)maskg)[tid]; if (w & 0xffffff00u) bad = 1; }
    const int m32 = __syncthreads_or(bad) ? 0 : 1;

    const size_t mask_row0 = (size_t)(b * SQ + qt * 64);

    // ---- cp.async prefetch of tile kt into parity p (pure linear copies) ----
    auto issue_prefetch = [&](int kt, int p) {
        const size_t tbw = ((size_t)b * SQ + (size_t)kt * 32) * DD;
        const char* ksrc = (const char*)(g_K + tbw);
        const char* vsrc = (const char*)(g_V + tbw);
        const uint32_t kb = sb + OFF_K + p * 16384;
        const uint32_t vb = sb + OFF_V + p * 16384;
        #pragma unroll
        for (int j = 0; j < 8; j++) {
            int ci = tid + j * 128;                  // 1024 16B-chunks per tensor
            cp16(kb + ci * 16, ksrc + ci * 16);
            cp16(vb + ci * 16, vsrc + ci * 16);
        }
        if (!m32) {
            const uint8_t* msrc = (const uint8_t*)maskg + mask_row0 * SQ + (size_t)kt * 32;
            const uint32_t mb = sb + OFF_M + p * 2560;
            int r = tid >> 1, h = tid & 1;           // 64 rows x 2 chunks
            cp16(mb + r * M_PITCH + h * 16, msrc + (size_t)r * SQ + h * 16);
        }
        CP_COMMIT();
    };
    issue_prefetch(0, 0);

    // ---- stage Q (64x128), pair-permuted + swizzled, fp32 -> tf32 ----
    {
        const float* qsrc = Qg + ((size_t)(b * SQ + qt * 64)) * DD;
        #pragma unroll
        for (int i = 0; i < 16; i++) {
            int idx = tid + i * 128;
            int r = idx >> 5, f = idx & 31;
            float4 v = ((const float4*)(qsrc + (size_t)r * DD))[f];
            uint32_t xr = (r & 3) << 3;
            #pragma unroll
            for (int j = 0; j < 4; j++) {
                int c = 4 * f + j;
                uint32_t pp = (c & ~7) | ((c & 3) << 1) | ((c >> 2) & 1);
                Qs[r * 128 + (pp ^ xr)] = f2tf32(((const float*)&v)[j]);
            }
        }
    }

    // persistent accumulators: O tile (16 rows x 128 d per warp) + rowsums
    float o[16][4];
    #pragma unroll
    for (int nt = 0; nt < 16; nt++) { o[nt][0] = o[nt][1] = o[nt][2] = o[nt][3] = 0.0f; }
    float lsum0 = 0.0f, lsum1 = 0.0f;

    const int qb = wid * 16;                               // CTA-local row base
    const size_t qrow_g = (size_t)(b * SQ + qt * 64) + qb + g;

    const int srcA = (lane & 0x1C) | ((lane & 3) >> 1);    // C->A frag shuffle srcs
    const int srcB = srcA + 2;
    const bool sel = lane & 1;
    const uint32_t xg = (g & 3) << 3;

    for (int kt = 0; kt < 64; kt++) {
        const int p = kt & 1;
        uint32_t* const Ks = (uint32_t*)(smem + OFF_K + p * 16384);
        uint32_t* const Vs = (uint32_t*)(smem + OFF_V + p * 16384);
        uint8_t*  const Ms = (uint8_t*)(smem + OFF_M + p * 2560);

        CP_WAIT0();
        __syncthreads();

        // ---- int32 mask fallback: manual stage (packed to bytes) ----
        if (m32) {
            const int* msrc = (const int*)maskg;
            #pragma unroll
            for (int i = 0; i < 4; i++) {
                int lin = tid + i * 128;               // 512 groups of 4 ints
                int r = lin >> 3, gi = lin & 7;
                size_t off = (mask_row0 + r) * SQ + kt * 32 + 4 * gi;
                uint4 x = *(const uint4*)(msrc + off);
                uint32_t packed = (x.x & 0xffu) | ((x.y & 0xffu) << 8) |
                                  ((x.z & 0xffu) << 16) | ((x.w & 0xffu) << 24);
                *(uint32_t*)(Ms + r * M_PITCH + 4 * gi) = packed;
            }
            __syncthreads();
        }
        if (kt < 63) issue_prefetch(kt + 1, p ^ 1);

        // ---- QK^T: scores C (16 rows x 32 kpos per warp), LDS.64 frags ----
        float c[4][4];
        #pragma unroll
        for (int nt = 0; nt < 4; nt++) { c[nt][0] = c[nt][1] = c[nt][2] = c[nt][3] = 0.0f; }

        #pragma unroll
        for (int ks = 0; ks < 16; ks++) {
            const uint32_t pc = ((uint32_t)(8 * ks + 2 * t)) ^ xg;
            const uint2 a01 = *(const uint2*)(Qs + (qb + g) * 128 + pc);
            const uint2 a23 = *(const uint2*)(Qs + (qb + 8 + g) * 128 + pc);
            #pragma unroll
            for (int nt = 0; nt < 4; nt++) {
                const uint2 bb = *(const uint2*)(Ks + (8 * nt + g) * 128 + pc);
                mma_tf32(c[nt][0], c[nt][1], c[nt][2], c[nt][3],
                         a01.x, a23.x, a01.y, a23.y, bb.x, bb.y);
            }
        }

        // ---- softmax numerator: mask, exp, rowsum, attn write ----
        float* arow0 = attng + qrow_g * SQ + kt * 32;
        float* arow1 = arow0 + 8 * (size_t)SQ;
        const uint8_t* mrow0 = Ms + (qb + g) * M_PITCH;
        const uint8_t* mrow1 = Ms + (qb + 8 + g) * M_PITCH;
        #pragma unroll
        for (int nt = 0; nt < 4; nt++) {
            const int cb = 8 * nt + 2 * t;
            uint32_t m0 = *(const uint16_t*)(mrow0 + cb);
            uint32_t m1 = *(const uint16_t*)(mrow1 + cb);
            float e0 = (m0 & 0xffu) ? 0.0f : __expf(c[nt][0] * QK_SCALE);
            float e1 = (m0 >> 8)    ? 0.0f : __expf(c[nt][1] * QK_SCALE);
            float e2 = (m1 & 0xffu) ? 0.0f : __expf(c[nt][2] * QK_SCALE);
            float e3 = (m1 >> 8)    ? 0.0f : __expf(c[nt][3] * QK_SCALE);
            c[nt][0] = e0; c[nt][1] = e1; c[nt][2] = e2; c[nt][3] = e3;
            lsum0 += e0 + e1;
            lsum1 += e2 + e3;
            if (has_attn) {
                __stcs((float2*)(arow0 + cb), make_float2(e0, e1));
                __stcs((float2*)(arow1 + cb), make_float2(e2, e3));
            }
        }

        // ---- PV: O += E @ V. C-frag(ks) -> A-frag via shuffles. ----
        #pragma unroll
        for (int ks = 0; ks < 4; ks++) {
            float v00 = __shfl_sync(0xffffffffu, c[ks][0], srcA);
            float v01 = __shfl_sync(0xffffffffu, c[ks][1], srcA);
            float v20 = __shfl_sync(0xffffffffu, c[ks][2], srcA);
            float v21 = __shfl_sync(0xffffffffu, c[ks][3], srcA);
            float w00 = __shfl_sync(0xffffffffu, c[ks][0], srcB);
            float w01 = __shfl_sync(0xffffffffu, c[ks][1], srcB);
            float w20 = __shfl_sync(0xffffffffu, c[ks][2], srcB);
            float w21 = __shfl_sync(0xffffffffu, c[ks][3], srcB);
            const uint32_t a0 = f2tf32(sel ? v01 : v00);
            const uint32_t a1 = f2tf32(sel ? v21 : v20);
            const uint32_t a2 = f2tf32(sel ? w01 : w00);
            const uint32_t a3 = f2tf32(sel ? w21 : w20);
            const int vr0 = 8 * ks + t;
            const int vr4 = vr0 + 4;
            #pragma unroll
            for (int nt = 0; nt < 16; nt++) {
                const int cc = (8 * nt + g) ^ (t << 3);
                const uint32_t b0 = Vs[vr0 * 128 + cc];
                const uint32_t b1 = Vs[vr4 * 128 + cc];
                mma_tf32(o[nt][0], o[nt][1], o[nt][2], o[nt][3], a0, a1, a2, a3, b0, b1);
            }
        }
    }

    // ---- reduce rowsums across the quad ----
    lsum0 += __shfl_xor_sync(0xffffffffu, lsum0, 1);
    lsum0 += __shfl_xor_sync(0xffffffffu, lsum0, 2);
    lsum1 += __shfl_xor_sync(0xffffffffu, lsum1, 1);
    lsum1 += __shfl_xor_sync(0xffffffffu, lsum1, 2);
    const float inv0 = 1.0f / lsum0;
    const float inv1 = 1.0f / lsum1;

    // share per-row inv via SMEM (K buffers are dead now)
    float* sInv = (float*)(smem + OFF_K);
    __syncthreads();
    if (t == 0) {
        sInv[qb + g]     = inv0;
        sInv[qb + 8 + g] = inv1;
    }

    // ---- out = O / rowsum ----
    float* orow0 = outg + qrow_g * DD;
    float* orow1 = orow0 + 8 * (size_t)DD;
    #pragma unroll
    for (int nt = 0; nt < 16; nt++) {
        const int cb = 8 * nt + 2 * t;
        *(float2*)(orow0 + cb) = make_float2(o[nt][0] * inv0, o[nt][1] * inv0);
        *(float2*)(orow1 + cb) = make_float2(o[nt][2] * inv1, o[nt][3] * inv1);
    }

    // ---- fused normalization of this CTA's 64 attn rows ----
    if (has_attn) {
        __syncthreads();
        float4* ap = (float4*)attng + ((size_t)(b * SQ + qt * 64)) * 512;
        #pragma unroll 4
        for (int i = 0; i < 256; i++) {
            int idx = tid + i * 128;                  // 0..32767 float4
            int r = idx >> 9, cw = idx & 511;
            float inv = sInv[r];
            float4 v = __ldcs(ap + (size_t)r * 512 + cw);
            v.x *= inv; v.y *= inv; v.z *= inv; v.w *= inv;
            __stcs(ap + (size_t)r * 512 + cw, v);
        }
    }
}

// ============================================================================
// Launch
// ============================================================================
extern "C" void kernel_launch(void* const* d_in, const int* in_sizes, int n_in,
                              void* d_out, int out_size) {
    const float* Q = (const float*)d_in[0];
    const float* K = (const float*)d_in[1];
    const float* V = (const float*)d_in[2];
    const void*  M = d_in[3];

    float* out = (float*)d_out;
    const long long out_elems  = (long long)BB * SQ * DD;              // 4,194,304
    const long long attn_elems = (long long)BB * SQ * SQ;              // 67,108,864
    int has_attn = ((long long)out_size >= out_elems + attn_elems) ? 1 : 0;
    float* attn = has_attn ? (out + out_elems) : out;   // dummy ptr if unused

    cudaFuncSetAttribute(attn_kernel,
                         cudaFuncAttributeMaxDynamicSharedMemorySize, SMEM_TOTAL);

    cvt_kernel<<<dim3((BB * SQ * DD / 4) / 256, 2), 256>>>(K, V);
    attn_kernel<<<dim3(SQ / 64, BB), 128, SMEM_TOTAL>>>(Q, M, out, attn, has_attn);
}